// round 15
// baseline (speedup 1.0000x reference)
#include <cuda_runtime.h>
#include <cuda_fp16.h>
#include <cstdint>

#define N_TOK 2048
#define C_DIM 1024
#define H_DIM 2048
#define E_NUM 8
#define EPSF 1.1920929e-07f

// ---------------- scratch (static device globals; no allocs) ----------------
__device__ __half g_xt[N_TOK * C_DIM];
__device__ __half g_xs[N_TOK * C_DIM];
__device__ __half g_w1[E_NUM * H_DIM * C_DIM];
__device__ __half g_w2[E_NUM * C_DIM * H_DIM];
__device__ __half g_kw[H_DIM * C_DIM];
__device__ __half g_vw[C_DIM * H_DIM];
__device__ __half g_h[2 * N_TOK * H_DIM];
__device__ __half g_kk[N_TOK * H_DIM];
__device__ float g_contrib[2 * N_TOK * C_DIM];
__device__ float g_sg[N_TOK];
__device__ float g_scores[N_TOK * E_NUM];
__device__ int   g_cnt[E_NUM];
__device__ int   g_etok[E_NUM * N_TOK];
__device__ float g_ew[E_NUM * N_TOK];
__device__ int   g_eslot[E_NUM * N_TOK];

// ---------------- helpers ----------------
__device__ __forceinline__ unsigned smem_u32(const void* p) {
    unsigned a;
    asm("{ .reg .u64 t; cvta.to.shared.u64 t, %1; cvt.u32.u64 %0, t; }" : "=r"(a) : "l"(p));
    return a;
}

#define CP16(s, g) asm volatile("cp.async.cg.shared.global [%0], [%1], 16;" :: "r"(s), "l"(g))
#define CP_COMMIT() asm volatile("cp.async.commit_group;" ::: "memory")
#define CP_WAIT1() asm volatile("cp.async.wait_group 1;" ::: "memory")
#define CP_WAIT0() asm volatile("cp.async.wait_group 0;" ::: "memory")

__device__ __forceinline__ void ldsm4(unsigned& r0, unsigned& r1, unsigned& r2, unsigned& r3,
                                      unsigned a) {
    asm volatile("ldmatrix.sync.aligned.m8n8.x4.shared.b16 {%0,%1,%2,%3}, [%4];"
                 : "=r"(r0), "=r"(r1), "=r"(r2), "=r"(r3) : "r"(a));
}

__device__ __forceinline__ void hmma(float* c, const unsigned* a, const unsigned* b) {
    asm volatile(
        "mma.sync.aligned.m16n8k16.row.col.f32.f16.f16.f32 "
        "{%0,%1,%2,%3}, {%4,%5,%6,%7}, {%8,%9}, {%0,%1,%2,%3};"
        : "+f"(c[0]), "+f"(c[1]), "+f"(c[2]), "+f"(c[3])
        : "r"(a[0]), "r"(a[1]), "r"(a[2]), "r"(a[3]), "r"(b[0]), "r"(b[1]));
}

// ---------------- zero counters ----------------
__global__ void k_zero() {
    if (threadIdx.x < E_NUM) g_cnt[threadIdx.x] = 0;
}

// ========= merged front kernel: gate blocks (0..2047) + weight-conv blocks =========
#define CONV_BLOCKS 4608
__global__ void k_front(const float* __restrict__ x,
                        const float* __restrict__ gate_w,
                        const float* __restrict__ sgw,
                        const float4* __restrict__ w1, const float4* __restrict__ w2,
                        const float4* __restrict__ kw, const float4* __restrict__ vw) {
    const int tid = threadIdx.x;
    if (blockIdx.x >= N_TOK) {
        const int N1 = E_NUM * H_DIM * C_DIM / 4;
        const int N2 = N1 + E_NUM * C_DIM * H_DIM / 4;
        const int N3 = N2 + H_DIM * C_DIM / 4;
        const int N4 = N3 + C_DIM * H_DIM / 4;
        const int cb = blockIdx.x - N_TOK;
        const int stride = CONV_BLOCKS * 256;
        for (int i = cb * 256 + tid; i < N4; i += stride) {
            const float4* s;
            __half2* d;
            int j;
            if (i < N1)      { s = w1; d = (__half2*)g_w1; j = i; }
            else if (i < N2) { s = w2; d = (__half2*)g_w2; j = i - N1; }
            else if (i < N3) { s = kw; d = (__half2*)g_kw; j = i - N2; }
            else             { s = vw; d = (__half2*)g_vw; j = i - N3; }
            float4 v = s[j];
            d[2 * j] = __halves2half2(__float2half_rn(v.x), __float2half_rn(v.y));
            d[2 * j + 1] = __halves2half2(__float2half_rn(v.z), __float2half_rn(v.w));
        }
        return;
    }
    // ---- gate path: rmsnorm + routing for token n ----
    const int n = blockIdx.x, wid = tid >> 5, lid = tid & 31;
    __shared__ float part[10][8];
    __shared__ float sc[2];
    __shared__ float logits[9];

    float4 v = reinterpret_cast<const float4*>(x + (size_t)n * C_DIM)[tid];
    float ss = v.x * v.x + v.y * v.y + v.z * v.z + v.w * v.w;
#pragma unroll
    for (int o = 16; o; o >>= 1) ss += __shfl_xor_sync(0xffffffffu, ss, o);
    if (lid == 0) part[9][wid] = ss;
    __syncthreads();
    if (tid == 0) {
        float s = 0;
#pragma unroll
        for (int w = 0; w < 8; w++) s += part[9][w];
        float m1 = s * (1.0f / C_DIM);
        float r1 = rsqrtf(m1 + EPSF);
        sc[0] = r1;
        sc[1] = rsqrtf(m1 * r1 * r1 + EPSF);
    }
    __syncthreads();
    const float r1 = sc[0], r2 = sc[1];

    float4 xt = {v.x * r1, v.y * r1, v.z * r1, v.w * r1};
    float4 xs = {xt.x * r2, xt.y * r2, xt.z * r2, xt.w * r2};
    size_t base = (size_t)n * C_DIM + tid * 4;
    {
        __half2* p = (__half2*)(g_xt + base);
        p[0] = __halves2half2(__float2half_rn(xt.x), __float2half_rn(xt.y));
        p[1] = __halves2half2(__float2half_rn(xt.z), __float2half_rn(xt.w));
        __half2* q = (__half2*)(g_xs + base);
        q[0] = __halves2half2(__float2half_rn(xs.x), __float2half_rn(xs.y));
        q[1] = __halves2half2(__float2half_rn(xs.z), __float2half_rn(xs.w));
    }

    float acc[9];
#pragma unroll
    for (int e = 0; e < 8; e++) {
        float4 g = reinterpret_cast<const float4*>(gate_w + (size_t)e * C_DIM)[tid];
        acc[e] = xt.x * g.x + xt.y * g.y + xt.z * g.z + xt.w * g.w;
    }
    {
        float4 g = reinterpret_cast<const float4*>(sgw)[tid];
        acc[8] = xt.x * g.x + xt.y * g.y + xt.z * g.z + xt.w * g.w;
    }
#pragma unroll
    for (int e = 0; e < 9; e++) {
        float a = acc[e];
#pragma unroll
        for (int o = 16; o; o >>= 1) a += __shfl_xor_sync(0xffffffffu, a, o);
        if (lid == 0) part[e][wid] = a;
    }
    __syncthreads();
    if (wid == 0 && lid < 9) {
        float s = 0;
#pragma unroll
        for (int w = 0; w < 8; w++) s += part[lid][w];
        logits[lid] = s;
    }
    __syncthreads();

    if (tid == 0) {
        float mx = logits[0];
#pragma unroll
        for (int e = 1; e < 8; e++) mx = fmaxf(mx, logits[e]);
        float sum = 0.0f, sv[8];
#pragma unroll
        for (int e = 0; e < 8; e++) { sv[e] = expf(logits[e] - mx); sum += sv[e]; }
        float inv = 1.0f / sum;
#pragma unroll
        for (int e = 0; e < 8; e++) { sv[e] *= inv; g_scores[n * 8 + e] = sv[e]; }
        int i1 = 0;
#pragma unroll
        for (int e = 1; e < 8; e++) if (sv[e] > sv[i1]) i1 = e;
        int i2 = (i1 == 0) ? 1 : 0;
#pragma unroll
        for (int e = 0; e < 8; e++) if (e != i1 && sv[e] > sv[i2]) i2 = e;
        float wa = sv[i1], wb = sv[i2];
        float wi = 1.0f / (wa + wb + 1e-6f);
        int p1 = atomicAdd(&g_cnt[i1], 1);
        g_etok[i1 * N_TOK + p1] = n;
        g_ew[i1 * N_TOK + p1] = wa * wi;
        g_eslot[i1 * N_TOK + p1] = 2 * n;
        int p2 = atomicAdd(&g_cnt[i2], 1);
        g_etok[i2 * N_TOK + p2] = n;
        g_ew[i2 * N_TOK + p2] = wb * wi;
        g_eslot[i2 * N_TOK + p2] = 2 * n + 1;
        g_sg[n] = 1.0f / (1.0f + expf(-logits[8]));
    }
}

// ---------------- aux loss ----------------
__global__ void k_aux(float* __restrict__ out, int out_size) {
    const int tid = threadIdx.x;
    __shared__ float red[256];
    __shared__ float ssum[8];
    float loc[8] = {0, 0, 0, 0, 0, 0, 0, 0};
    for (int n = tid; n < N_TOK; n += 256) {
#pragma unroll
        for (int e = 0; e < 8; e++) loc[e] += g_scores[n * 8 + e];
    }
#pragma unroll 1
    for (int e = 0; e < 8; e++) {
        red[tid] = loc[e];
        __syncthreads();
        for (int s = 128; s > 0; s >>= 1) {
            if (tid < s) red[tid] += red[tid + s];
            __syncthreads();
        }
        if (tid == 0) ssum[e] = red[0];
        __syncthreads();
    }
    if (tid == 0) {
        float aux = 0.0f;
#pragma unroll
        for (int e = 0; e < 8; e++)
            aux += ((float)g_cnt[e] * 0.5f / N_TOK) * (ssum[e] / N_TOK);
        aux *= (float)E_NUM * 0.01f;
        if (out_size > N_TOK * C_DIM) out[N_TOK * C_DIM] = aux;
    }
}

// ================= HMMA fp16 single-pass GEMM, 2-stage pipeline, BK=64 =======
// CTA tile 128 x 64, BK=64, 256 thr, warp grid 4(M)x2(N) -> warp tile 32x32.
// 3 CTAs/SM (reg cap 85) -> 24 warps/SM.
#define BKC 64
#define ROWB 144                 // 128B data + 16B pad; conflict-free ldmatrix
#define TN 64

// MODE 0: merged up. z<8: expert up (A=xt, B=w1[z], relu^2*w -> g_h[slot]);
//                    z==8: shared up (A=xs, B=kw, (x+kb) relu^2 -> g_kk). K=1024.
// MODE 1: expert down A=h  B=w2[e] K=2048 -> contrib (fp32)
// MODE 3: shared down A=kk B=vw   K=2048 -> out = sg*(x+vb) + contrib0 + contrib1
template <int MODE>
__global__ void __launch_bounds__(256, 3) k_mma(const float* __restrict__ bias,
                                                float* __restrict__ outp) {
    constexpr int WTM = 32;
    constexpr int WTN = 32;
    constexpr int MF = 2;
    constexpr int NF = 4;
    constexpr int A_SZ = 128 * ROWB;
    constexpr int B_SZ = TN * ROWB;
    constexpr int SA = 0;
    constexpr int SB = A_SZ;
    constexpr int BUF_SZ = A_SZ + B_SZ;

    extern __shared__ char dsm[];
    __shared__ int s_row[128];
    __shared__ int s_slot[128];
    __shared__ float s_w[128];

    const int e = blockIdx.z;
    const bool shared_path = (MODE == 0 && e == 8);
    const int cnt = (MODE == 0 && !shared_path) ? g_cnt[e]
                  : (MODE == 1) ? g_cnt[e] : N_TOK;
    const int m0 = blockIdx.y * 128;
    if (m0 >= cnt) return;
    const int n0 = blockIdx.x * TN;
    const int K = (MODE == 0) ? C_DIM : H_DIM;

    const __half *A, *B;
    if (MODE == 0) {
        if (shared_path) { A = g_xs; B = g_kw; }
        else { A = g_xt; B = g_w1 + (size_t)e * H_DIM * C_DIM; }
    } else if (MODE == 1) {
        A = g_h; B = g_w2 + (size_t)e * C_DIM * H_DIM;
    } else {
        A = g_kk; B = g_vw;
    }

    const int tid = threadIdx.x, wid = tid >> 5, lid = tid & 31;
    const int wm = wid >> 1, wn = wid & 1;

    if (tid < 128) {
        int mi = m0 + tid;
        if (mi >= cnt) mi = cnt - 1;
        if (MODE == 0 && !shared_path) {
            s_row[tid] = g_etok[e * N_TOK + mi];
            s_slot[tid] = g_eslot[e * N_TOK + mi];
            s_w[tid] = g_ew[e * N_TOK + mi];
        } else if (MODE == 1) {
            int sl = g_eslot[e * N_TOK + mi];
            s_row[tid] = sl;
            s_slot[tid] = sl;
        } else {
            s_row[tid] = mi;
        }
    }
    __syncthreads();

    const unsigned sbase = smem_u32(dsm);
    const int lr = tid >> 3;          // 0..31: row group (32 rows per pass)
    const int lcb = (tid & 7) << 4;   // byte col 0..112
    const int lce = (tid & 7) << 3;   // elem col 0..56

    auto load_chunk = [&](int c, int b) {
        const int kc = c * BKC;
        const unsigned bufb = sbase + b * BUF_SZ;
#pragma unroll
        for (int i = 0; i < 4; i++) {           // A: 128 rows
            const int r = lr + i * 32;
            const unsigned so = r * ROWB + lcb;
            const size_t ga = (size_t)s_row[r] * K + kc + lce;
            CP16(bufb + SA + so, A + ga);
        }
#pragma unroll
        for (int i = 0; i < 2; i++) {           // B: 64 rows
            const int r = lr + i * 32;
            const unsigned so = r * ROWB + lcb;
            const size_t gb = (size_t)(n0 + r) * K + kc + lce;
            CP16(bufb + SB + so, B + gb);
        }
        CP_COMMIT();
    };

    float acc[MF][NF][4];
#pragma unroll
    for (int i = 0; i < MF; i++)
#pragma unroll
        for (int j = 0; j < NF; j++)
#pragma unroll
            for (int q = 0; q < 4; q++) acc[i][j][q] = 0.0f;

    const unsigned aoff = (unsigned)((wm * WTM + (lid & 7) + ((lid >> 3) & 1) * 8) * ROWB +
                                     ((lid >> 4) & 1) * 16);
    const unsigned boff = (unsigned)((wn * WTN + (lid & 7) + ((lid >> 4) & 1) * 8) * ROWB +
                                     ((lid >> 3) & 1) * 16);
    const int NC = K / BKC;
    load_chunk(0, 0);

    for (int c = 0; c < NC; c++) {
        const int b = c & 1;
        if (c + 1 < NC) { load_chunk(c + 1, b ^ 1); CP_WAIT1(); }
        else CP_WAIT0();
        __syncthreads();
        const unsigned bufb = sbase + b * BUF_SZ;
#pragma unroll
        for (int k16 = 0; k16 < 4; k16++) {     // BK=64 -> 4 k16 steps
            const unsigned kb = k16 * 32;
            unsigned af[MF][4], bf[NF][2];
#pragma unroll
            for (int pr = 0; pr < NF / 2; pr++) {
                const unsigned a = bufb + boff + pr * (16 * ROWB) + kb;
                ldsm4(bf[2 * pr][0], bf[2 * pr][1], bf[2 * pr + 1][0], bf[2 * pr + 1][1], a + SB);
            }
#pragma unroll
            for (int mt = 0; mt < MF; mt++) {
                const unsigned a = bufb + aoff + mt * (16 * ROWB) + kb;
                ldsm4(af[mt][0], af[mt][1], af[mt][2], af[mt][3], a + SA);
            }
#pragma unroll
            for (int mt = 0; mt < MF; mt++)
#pragma unroll
                for (int nt = 0; nt < NF; nt++) hmma(acc[mt][nt], af[mt], bf[nt]);
        }
        __syncthreads();
    }

    // ---------------- epilogue ----------------
    const int rbase = wm * WTM + (lid >> 2);
    const int cbase = n0 + wn * WTN + 2 * (lid & 3);
#pragma unroll
    for (int mt = 0; mt < MF; mt++) {
#pragma unroll
        for (int half = 0; half < 2; half++) {
            const int rl = rbase + mt * 16 + half * 8;   // local row 0..127
            if (m0 + rl >= cnt) continue;
#pragma unroll
            for (int nt = 0; nt < NF; nt++) {
                const int cg = cbase + nt * 8;
                float v0 = acc[mt][nt][2 * half];
                float v1 = acc[mt][nt][2 * half + 1];
                if (MODE == 0) {
                    if (!shared_path) {
                        const float w = s_w[rl];
                        const int slot = s_slot[rl];
                        v0 = fmaxf(v0, 0.0f); v0 = v0 * v0 * w;
                        v1 = fmaxf(v1, 0.0f); v1 = v1 * v1 * w;
                        *(__half2*)(g_h + (size_t)slot * H_DIM + cg) =
                            __halves2half2(__float2half_rn(v0), __float2half_rn(v1));
                    } else {
                        const int m = m0 + rl;
                        v0 += bias[cg]; v1 += bias[cg + 1];
                        v0 = fmaxf(v0, 0.0f); v0 = v0 * v0;
                        v1 = fmaxf(v1, 0.0f); v1 = v1 * v1;
                        *(__half2*)(g_kk + (size_t)m * H_DIM + cg) =
                            __halves2half2(__float2half_rn(v0), __float2half_rn(v1));
                    }
                } else if (MODE == 1) {
                    const int slot = s_slot[rl];
                    *(float2*)(g_contrib + (size_t)slot * C_DIM + cg) = make_float2(v0, v1);
                } else {
                    const int m = m0 + rl;
                    const float sg = g_sg[m];
                    float2 c0 = *(const float2*)(g_contrib + (size_t)(2 * m) * C_DIM + cg);
                    float2 c1 = *(const float2*)(g_contrib + (size_t)(2 * m + 1) * C_DIM + cg);
                    *(float2*)(outp + (size_t)m * C_DIM + cg) =
                        make_float2(sg * (v0 + bias[cg]) + c0.x + c1.x,
                                    sg * (v1 + bias[cg + 1]) + c0.y + c1.y);
                }
            }
        }
    }
}

// ---------------- launch ----------------
#define DS_TILE (2 * (128 * ROWB + TN * ROWB))   // 55296, OCC=3

extern "C" void kernel_launch(void* const* d_in, const int* in_sizes, int n_in,
                              void* d_out, int out_size) {
    const float* x   = (const float*)d_in[0];
    const float* gw  = (const float*)d_in[1];
    const float* w1  = (const float*)d_in[2];
    const float* w2  = (const float*)d_in[3];
    const float* sgw = (const float*)d_in[4];
    const float* kw  = (const float*)d_in[5];
    const float* kb  = (const float*)d_in[6];
    const float* vw  = (const float*)d_in[7];
    const float* vb  = (const float*)d_in[8];
    float* out = (float*)d_out;

    static int attr_done = 0;
    if (!attr_done) {
        cudaFuncSetAttribute((const void*)k_mma<0>,
                             cudaFuncAttributeMaxDynamicSharedMemorySize, DS_TILE);
        cudaFuncSetAttribute((const void*)k_mma<1>,
                             cudaFuncAttributeMaxDynamicSharedMemorySize, DS_TILE);
        cudaFuncSetAttribute((const void*)k_mma<3>,
                             cudaFuncAttributeMaxDynamicSharedMemorySize, DS_TILE);
        attr_done = 1;
    }

    k_zero<<<1, 32>>>();
    k_front<<<N_TOK + CONV_BLOCKS, 256>>>(x, gw, sgw,
                                          (const float4*)w1, (const float4*)w2,
                                          (const float4*)kw, (const float4*)vw);
    k_aux<<<1, 256>>>(out, out_size);

    k_mma<0><<<dim3(32, 16, 9), 256, DS_TILE>>>(kb, nullptr);      // expert up + shared up
    k_mma<1><<<dim3(16, 16, 8), 256, DS_TILE>>>(nullptr, nullptr); // expert down
    k_mma<3><<<dim3(16, 16, 1), 256, DS_TILE>>>(vb, out);          // shared down + combine
}

// round 16
// speedup vs baseline: 1.2055x; 1.2055x over previous
#include <cuda_runtime.h>
#include <cuda_fp16.h>
#include <cstdint>

#define N_TOK 2048
#define C_DIM 1024
#define H_DIM 2048
#define E_NUM 8
#define EPSF 1.1920929e-07f

// ---------------- scratch (static device globals; no allocs) ----------------
__device__ __half g_xt[N_TOK * C_DIM];
__device__ __half g_xs[N_TOK * C_DIM];
__device__ __half g_w1[E_NUM * H_DIM * C_DIM];
__device__ __half g_w2[E_NUM * C_DIM * H_DIM];
__device__ __half g_kw[H_DIM * C_DIM];
__device__ __half g_vw[C_DIM * H_DIM];
__device__ __half g_h[2 * N_TOK * H_DIM];
__device__ __half g_kk[N_TOK * H_DIM];
__device__ float g_contrib[2 * N_TOK * C_DIM];
__device__ float g_sg[N_TOK];
__device__ float g_scores[N_TOK * E_NUM];
__device__ int   g_cnt[E_NUM];
__device__ int   g_etok[E_NUM * N_TOK];
__device__ float g_ew[E_NUM * N_TOK];
__device__ int   g_eslot[E_NUM * N_TOK];

// ---------------- helpers ----------------
__device__ __forceinline__ unsigned smem_u32(const void* p) {
    unsigned a;
    asm("{ .reg .u64 t; cvta.to.shared.u64 t, %1; cvt.u32.u64 %0, t; }" : "=r"(a) : "l"(p));
    return a;
}

#define CP16(s, g) asm volatile("cp.async.cg.shared.global [%0], [%1], 16;" :: "r"(s), "l"(g))
#define CP_COMMIT() asm volatile("cp.async.commit_group;" ::: "memory")
#define CP_WAIT1() asm volatile("cp.async.wait_group 1;" ::: "memory")
#define CP_WAIT0() asm volatile("cp.async.wait_group 0;" ::: "memory")

__device__ __forceinline__ void ldsm4(unsigned& r0, unsigned& r1, unsigned& r2, unsigned& r3,
                                      unsigned a) {
    asm volatile("ldmatrix.sync.aligned.m8n8.x4.shared.b16 {%0,%1,%2,%3}, [%4];"
                 : "=r"(r0), "=r"(r1), "=r"(r2), "=r"(r3) : "r"(a));
}

__device__ __forceinline__ void hmma(float* c, const unsigned* a, const unsigned* b) {
    asm volatile(
        "mma.sync.aligned.m16n8k16.row.col.f32.f16.f16.f32 "
        "{%0,%1,%2,%3}, {%4,%5,%6,%7}, {%8,%9}, {%0,%1,%2,%3};"
        : "+f"(c[0]), "+f"(c[1]), "+f"(c[2]), "+f"(c[3])
        : "r"(a[0]), "r"(a[1]), "r"(a[2]), "r"(a[3]), "r"(b[0]), "r"(b[1]));
}

// ---------------- zero counters ----------------
__global__ void k_zero() {
    if (threadIdx.x < E_NUM) g_cnt[threadIdx.x] = 0;
}

// ========= merged front kernel: gate blocks (0..2047) + weight-conv blocks =========
#define CONV_BLOCKS 4608
__global__ void k_front(const float* __restrict__ x,
                        const float* __restrict__ gate_w,
                        const float* __restrict__ sgw,
                        const float4* __restrict__ w1, const float4* __restrict__ w2,
                        const float4* __restrict__ kw, const float4* __restrict__ vw) {
    const int tid = threadIdx.x;
    if (blockIdx.x >= N_TOK) {
        const int N1 = E_NUM * H_DIM * C_DIM / 4;
        const int N2 = N1 + E_NUM * C_DIM * H_DIM / 4;
        const int N3 = N2 + H_DIM * C_DIM / 4;
        const int N4 = N3 + C_DIM * H_DIM / 4;
        const int cb = blockIdx.x - N_TOK;
        const int stride = CONV_BLOCKS * 256;
        for (int i = cb * 256 + tid; i < N4; i += stride) {
            const float4* s;
            __half2* d;
            int j;
            if (i < N1)      { s = w1; d = (__half2*)g_w1; j = i; }
            else if (i < N2) { s = w2; d = (__half2*)g_w2; j = i - N1; }
            else if (i < N3) { s = kw; d = (__half2*)g_kw; j = i - N2; }
            else             { s = vw; d = (__half2*)g_vw; j = i - N3; }
            float4 v = s[j];
            d[2 * j] = __halves2half2(__float2half_rn(v.x), __float2half_rn(v.y));
            d[2 * j + 1] = __halves2half2(__float2half_rn(v.z), __float2half_rn(v.w));
        }
        return;
    }
    // ---- gate path: rmsnorm + routing for token n ----
    const int n = blockIdx.x, wid = tid >> 5, lid = tid & 31;
    __shared__ float part[10][8];
    __shared__ float sc[2];
    __shared__ float logits[9];

    float4 v = reinterpret_cast<const float4*>(x + (size_t)n * C_DIM)[tid];
    float ss = v.x * v.x + v.y * v.y + v.z * v.z + v.w * v.w;
#pragma unroll
    for (int o = 16; o; o >>= 1) ss += __shfl_xor_sync(0xffffffffu, ss, o);
    if (lid == 0) part[9][wid] = ss;
    __syncthreads();
    if (tid == 0) {
        float s = 0;
#pragma unroll
        for (int w = 0; w < 8; w++) s += part[9][w];
        float m1 = s * (1.0f / C_DIM);
        float r1 = rsqrtf(m1 + EPSF);
        sc[0] = r1;
        sc[1] = rsqrtf(m1 * r1 * r1 + EPSF);
    }
    __syncthreads();
    const float r1 = sc[0], r2 = sc[1];

    float4 xt = {v.x * r1, v.y * r1, v.z * r1, v.w * r1};
    float4 xs = {xt.x * r2, xt.y * r2, xt.z * r2, xt.w * r2};
    size_t base = (size_t)n * C_DIM + tid * 4;
    {
        __half2* p = (__half2*)(g_xt + base);
        p[0] = __halves2half2(__float2half_rn(xt.x), __float2half_rn(xt.y));
        p[1] = __halves2half2(__float2half_rn(xt.z), __float2half_rn(xt.w));
        __half2* q = (__half2*)(g_xs + base);
        q[0] = __halves2half2(__float2half_rn(xs.x), __float2half_rn(xs.y));
        q[1] = __halves2half2(__float2half_rn(xs.z), __float2half_rn(xs.w));
    }

    float acc[9];
#pragma unroll
    for (int e = 0; e < 8; e++) {
        float4 g = reinterpret_cast<const float4*>(gate_w + (size_t)e * C_DIM)[tid];
        acc[e] = xt.x * g.x + xt.y * g.y + xt.z * g.z + xt.w * g.w;
    }
    {
        float4 g = reinterpret_cast<const float4*>(sgw)[tid];
        acc[8] = xt.x * g.x + xt.y * g.y + xt.z * g.z + xt.w * g.w;
    }
#pragma unroll
    for (int e = 0; e < 9; e++) {
        float a = acc[e];
#pragma unroll
        for (int o = 16; o; o >>= 1) a += __shfl_xor_sync(0xffffffffu, a, o);
        if (lid == 0) part[e][wid] = a;
    }
    __syncthreads();
    if (wid == 0 && lid < 9) {
        float s = 0;
#pragma unroll
        for (int w = 0; w < 8; w++) s += part[lid][w];
        logits[lid] = s;
    }
    __syncthreads();

    if (tid == 0) {
        float mx = logits[0];
#pragma unroll
        for (int e = 1; e < 8; e++) mx = fmaxf(mx, logits[e]);
        float sum = 0.0f, sv[8];
#pragma unroll
        for (int e = 0; e < 8; e++) { sv[e] = expf(logits[e] - mx); sum += sv[e]; }
        float inv = 1.0f / sum;
#pragma unroll
        for (int e = 0; e < 8; e++) { sv[e] *= inv; g_scores[n * 8 + e] = sv[e]; }
        int i1 = 0;
#pragma unroll
        for (int e = 1; e < 8; e++) if (sv[e] > sv[i1]) i1 = e;
        int i2 = (i1 == 0) ? 1 : 0;
#pragma unroll
        for (int e = 0; e < 8; e++) if (e != i1 && sv[e] > sv[i2]) i2 = e;
        float wa = sv[i1], wb = sv[i2];
        float wi = 1.0f / (wa + wb + 1e-6f);
        int p1 = atomicAdd(&g_cnt[i1], 1);
        g_etok[i1 * N_TOK + p1] = n;
        g_ew[i1 * N_TOK + p1] = wa * wi;
        g_eslot[i1 * N_TOK + p1] = 2 * n;
        int p2 = atomicAdd(&g_cnt[i2], 1);
        g_etok[i2 * N_TOK + p2] = n;
        g_ew[i2 * N_TOK + p2] = wb * wi;
        g_eslot[i2 * N_TOK + p2] = 2 * n + 1;
        g_sg[n] = 1.0f / (1.0f + expf(-logits[8]));
    }
}

// ---------------- aux loss ----------------
__global__ void k_aux(float* __restrict__ out, int out_size) {
    const int tid = threadIdx.x;
    __shared__ float red[256];
    __shared__ float ssum[8];
    float loc[8] = {0, 0, 0, 0, 0, 0, 0, 0};
    for (int n = tid; n < N_TOK; n += 256) {
#pragma unroll
        for (int e = 0; e < 8; e++) loc[e] += g_scores[n * 8 + e];
    }
#pragma unroll 1
    for (int e = 0; e < 8; e++) {
        red[tid] = loc[e];
        __syncthreads();
        for (int s = 128; s > 0; s >>= 1) {
            if (tid < s) red[tid] += red[tid + s];
            __syncthreads();
        }
        if (tid == 0) ssum[e] = red[0];
        __syncthreads();
    }
    if (tid == 0) {
        float aux = 0.0f;
#pragma unroll
        for (int e = 0; e < 8; e++)
            aux += ((float)g_cnt[e] * 0.5f / N_TOK) * (ssum[e] / N_TOK);
        aux *= (float)E_NUM * 0.01f;
        if (out_size > N_TOK * C_DIM) out[N_TOK * C_DIM] = aux;
    }
}

// ===== HMMA fp16 single-pass GEMM, 3-stage ring / 1 barrier per chunk, BK=64 =====
// CTA tile 128 x TN, BK=64, 256 thr.
// TN=128: warp grid 4(M)x2(N), warp tile 32x64, OCC=2 (16 warps/SM).
// TN=64 : warp grid 4(M)x2(N), warp tile 32x32, OCC=2.
#define BKC 64
#define ROWB 144                 // 128B data + 16B pad; conflict-free ldmatrix
#define STAGES 3

// MODE 0: merged up. z<8: expert up (A=xt, B=w1[z], relu^2*w -> g_h[slot]);
//                    z==8: shared up (A=xs, B=kw, (x+kb) relu^2 -> g_kk). K=1024.
// MODE 1: expert down A=h  B=w2[e] K=2048 -> contrib (fp32)
// MODE 3: shared down A=kk B=vw   K=2048 -> out = sg*(x+vb) + contrib0 + contrib1
template <int MODE, int TN>
__global__ void __launch_bounds__(256, 2) k_mma(const float* __restrict__ bias,
                                                float* __restrict__ outp) {
    constexpr int W_M = 4;
    constexpr int W_N = 2;
    constexpr int WTM = 128 / W_M;               // 32
    constexpr int WTN = TN / W_N;                // 64 or 32
    constexpr int MF = WTM / 16;                 // 2
    constexpr int NF = WTN / 8;                  // 8 or 4
    constexpr int A_SZ = 128 * ROWB;
    constexpr int B_SZ = TN * ROWB;
    constexpr int SA = 0;
    constexpr int SB = A_SZ;
    constexpr int BUF_SZ = A_SZ + B_SZ;

    extern __shared__ char dsm[];
    __shared__ int s_row[128];
    __shared__ int s_slot[128];
    __shared__ float s_w[128];

    const int e = blockIdx.z;
    const bool shared_path = (MODE == 0 && e == 8);
    const int cnt = (MODE == 0 && !shared_path) ? g_cnt[e]
                  : (MODE == 1) ? g_cnt[e] : N_TOK;
    const int m0 = blockIdx.y * 128;
    if (m0 >= cnt) return;
    const int n0 = blockIdx.x * TN;
    const int K = (MODE == 0) ? C_DIM : H_DIM;

    const __half *A, *B;
    if (MODE == 0) {
        if (shared_path) { A = g_xs; B = g_kw; }
        else { A = g_xt; B = g_w1 + (size_t)e * H_DIM * C_DIM; }
    } else if (MODE == 1) {
        A = g_h; B = g_w2 + (size_t)e * C_DIM * H_DIM;
    } else {
        A = g_kk; B = g_vw;
    }

    const int tid = threadIdx.x, wid = tid >> 5, lid = tid & 31;
    const int wm = wid / W_N, wn = wid % W_N;

    if (tid < 128) {
        int mi = m0 + tid;
        if (mi >= cnt) mi = cnt - 1;
        if (MODE == 0 && !shared_path) {
            s_row[tid] = g_etok[e * N_TOK + mi];
            s_slot[tid] = g_eslot[e * N_TOK + mi];
            s_w[tid] = g_ew[e * N_TOK + mi];
        } else if (MODE == 1) {
            int sl = g_eslot[e * N_TOK + mi];
            s_row[tid] = sl;
            s_slot[tid] = sl;
        } else {
            s_row[tid] = mi;
        }
    }
    __syncthreads();

    const unsigned sbase = smem_u32(dsm);
    const int lr = tid >> 3;          // 0..31: row group (32 rows per pass)
    const int lcb = (tid & 7) << 4;   // byte col 0..112
    const int lce = (tid & 7) << 3;   // elem col 0..56

    auto load_chunk = [&](int c, int b) {
        const int kc = c * BKC;
        const unsigned bufb = sbase + b * BUF_SZ;
#pragma unroll
        for (int i = 0; i < 4; i++) {           // A: 128 rows
            const int r = lr + i * 32;
            const unsigned so = r * ROWB + lcb;
            const size_t ga = (size_t)s_row[r] * K + kc + lce;
            CP16(bufb + SA + so, A + ga);
        }
#pragma unroll
        for (int i = 0; i < TN / 32; i++) {     // B: TN rows
            const int r = lr + i * 32;
            const unsigned so = r * ROWB + lcb;
            const size_t gb = (size_t)(n0 + r) * K + kc + lce;
            CP16(bufb + SB + so, B + gb);
        }
        CP_COMMIT();
    };

    float acc[MF][NF][4];
#pragma unroll
    for (int i = 0; i < MF; i++)
#pragma unroll
        for (int j = 0; j < NF; j++)
#pragma unroll
            for (int q = 0; q < 4; q++) acc[i][j][q] = 0.0f;

    const unsigned aoff = (unsigned)((wm * WTM + (lid & 7) + ((lid >> 3) & 1) * 8) * ROWB +
                                     ((lid >> 4) & 1) * 16);
    const unsigned boff = (unsigned)((wn * WTN + (lid & 7) + ((lid >> 4) & 1) * 8) * ROWB +
                                     ((lid >> 3) & 1) * 16);
    const int NC = K / BKC;
    load_chunk(0, 0);

    int buf = 0;
    for (int c = 0; c < NC; c++) {
        // issue next chunk into ring slot (c+1)%3 — safe: that slot was consumed
        // at iter c-2 and all warps passed iter c-1's barrier after computing it.
        if (c + 1 < NC) { load_chunk(c + 1, (c + 1) % STAGES); CP_WAIT1(); }
        else CP_WAIT0();
        __syncthreads();                         // single barrier per chunk
        const unsigned bufb = sbase + buf * BUF_SZ;
#pragma unroll
        for (int k16 = 0; k16 < 4; k16++) {      // BK=64 -> 4 k16 steps
            const unsigned kb = k16 * 32;
            unsigned af[MF][4], bf[NF][2];
#pragma unroll
            for (int pr = 0; pr < NF / 2; pr++) {
                const unsigned a = bufb + boff + pr * (16 * ROWB) + kb;
                ldsm4(bf[2 * pr][0], bf[2 * pr][1], bf[2 * pr + 1][0], bf[2 * pr + 1][1], a + SB);
            }
#pragma unroll
            for (int mt = 0; mt < MF; mt++) {
                const unsigned a = bufb + aoff + mt * (16 * ROWB) + kb;
                ldsm4(af[mt][0], af[mt][1], af[mt][2], af[mt][3], a + SA);
            }
#pragma unroll
            for (int mt = 0; mt < MF; mt++)
#pragma unroll
                for (int nt = 0; nt < NF; nt++) hmma(acc[mt][nt], af[mt], bf[nt]);
        }
        buf = (buf + 1) % STAGES;
    }

    // ---------------- epilogue ----------------
    const int rbase = wm * WTM + (lid >> 2);
    const int cbase = n0 + wn * WTN + 2 * (lid & 3);
#pragma unroll
    for (int mt = 0; mt < MF; mt++) {
#pragma unroll
        for (int half = 0; half < 2; half++) {
            const int rl = rbase + mt * 16 + half * 8;   // local row 0..127
            if (m0 + rl >= cnt) continue;
#pragma unroll
            for (int nt = 0; nt < NF; nt++) {
                const int cg = cbase + nt * 8;
                float v0 = acc[mt][nt][2 * half];
                float v1 = acc[mt][nt][2 * half + 1];
                if (MODE == 0) {
                    if (!shared_path) {
                        const float w = s_w[rl];
                        const int slot = s_slot[rl];
                        v0 = fmaxf(v0, 0.0f); v0 = v0 * v0 * w;
                        v1 = fmaxf(v1, 0.0f); v1 = v1 * v1 * w;
                        *(__half2*)(g_h + (size_t)slot * H_DIM + cg) =
                            __halves2half2(__float2half_rn(v0), __float2half_rn(v1));
                    } else {
                        const int m = m0 + rl;
                        v0 += bias[cg]; v1 += bias[cg + 1];
                        v0 = fmaxf(v0, 0.0f); v0 = v0 * v0;
                        v1 = fmaxf(v1, 0.0f); v1 = v1 * v1;
                        *(__half2*)(g_kk + (size_t)m * H_DIM + cg) =
                            __halves2half2(__float2half_rn(v0), __float2half_rn(v1));
                    }
                } else if (MODE == 1) {
                    const int slot = s_slot[rl];
                    *(float2*)(g_contrib + (size_t)slot * C_DIM + cg) = make_float2(v0, v1);
                } else {
                    const int m = m0 + rl;
                    const float sg = g_sg[m];
                    float2 c0 = *(const float2*)(g_contrib + (size_t)(2 * m) * C_DIM + cg);
                    float2 c1 = *(const float2*)(g_contrib + (size_t)(2 * m + 1) * C_DIM + cg);
                    *(float2*)(outp + (size_t)m * C_DIM + cg) =
                        make_float2(sg * (v0 + bias[cg]) + c0.x + c1.x,
                                    sg * (v1 + bias[cg + 1]) + c0.y + c1.y);
                }
            }
        }
    }
}

// ---------------- launch ----------------
#define DS128 (STAGES * (128 * ROWB + 128 * ROWB))   // 110592, OCC=2
#define DS64  (STAGES * (128 * ROWB + 64 * ROWB))    // 82944, OCC=2

extern "C" void kernel_launch(void* const* d_in, const int* in_sizes, int n_in,
                              void* d_out, int out_size) {
    const float* x   = (const float*)d_in[0];
    const float* gw  = (const float*)d_in[1];
    const float* w1  = (const float*)d_in[2];
    const float* w2  = (const float*)d_in[3];
    const float* sgw = (const float*)d_in[4];
    const float* kw  = (const float*)d_in[5];
    const float* kb  = (const float*)d_in[6];
    const float* vw  = (const float*)d_in[7];
    const float* vb  = (const float*)d_in[8];
    float* out = (float*)d_out;

    static int attr_done = 0;
    if (!attr_done) {
        cudaFuncSetAttribute((const void*)k_mma<0, 128>,
                             cudaFuncAttributeMaxDynamicSharedMemorySize, DS128);
        cudaFuncSetAttribute((const void*)k_mma<1, 128>,
                             cudaFuncAttributeMaxDynamicSharedMemorySize, DS128);
        cudaFuncSetAttribute((const void*)k_mma<3, 64>,
                             cudaFuncAttributeMaxDynamicSharedMemorySize, DS64);
        attr_done = 1;
    }

    k_zero<<<1, 32>>>();
    k_front<<<N_TOK + CONV_BLOCKS, 256>>>(x, gw, sgw,
                                          (const float4*)w1, (const float4*)w2,
                                          (const float4*)kw, (const float4*)vw);
    k_aux<<<1, 256>>>(out, out_size);

    k_mma<0, 128><<<dim3(16, 16, 9), 256, DS128>>>(kb, nullptr);      // expert up + shared up
    k_mma<1, 128><<<dim3(8, 16, 8), 256, DS128>>>(nullptr, nullptr);  // expert down
    k_mma<3, 64><<<dim3(16, 16, 1), 256, DS64>>>(vb, out);            // shared down + combine
}

// round 17
// speedup vs baseline: 1.2782x; 1.0603x over previous
#include <cuda_runtime.h>
#include <cuda_fp16.h>
#include <cstdint>

#define N_TOK 2048
#define C_DIM 1024
#define H_DIM 2048
#define E_NUM 8
#define EPSF 1.1920929e-07f

// ---------------- scratch (static device globals; no allocs) ----------------
__device__ __half g_xt[N_TOK * C_DIM];
__device__ __half g_xs[N_TOK * C_DIM];
__device__ __half g_w1[E_NUM * H_DIM * C_DIM];
__device__ __half g_w2[E_NUM * C_DIM * H_DIM];
__device__ __half g_kw[H_DIM * C_DIM];
__device__ __half g_vw[C_DIM * H_DIM];
__device__ __half g_h[2 * N_TOK * H_DIM];
__device__ __half g_kk[N_TOK * H_DIM];
__device__ float g_contrib[2 * N_TOK * C_DIM];
__device__ float g_sg[N_TOK];
__device__ float g_scores[N_TOK * E_NUM];
__device__ int   g_cnt[E_NUM];
__device__ int   g_etok[E_NUM * N_TOK];
__device__ float g_ew[E_NUM * N_TOK];
__device__ int   g_eslot[E_NUM * N_TOK];

// ---------------- helpers ----------------
__device__ __forceinline__ unsigned smem_u32(const void* p) {
    unsigned a;
    asm("{ .reg .u64 t; cvta.to.shared.u64 t, %1; cvt.u32.u64 %0, t; }" : "=r"(a) : "l"(p));
    return a;
}

#define CP16(s, g) asm volatile("cp.async.cg.shared.global [%0], [%1], 16;" :: "r"(s), "l"(g))
#define CP_COMMIT() asm volatile("cp.async.commit_group;" ::: "memory")
#define CP_WAIT1() asm volatile("cp.async.wait_group 1;" ::: "memory")
#define CP_WAIT0() asm volatile("cp.async.wait_group 0;" ::: "memory")

__device__ __forceinline__ void ldsm4(unsigned& r0, unsigned& r1, unsigned& r2, unsigned& r3,
                                      unsigned a) {
    asm volatile("ldmatrix.sync.aligned.m8n8.x4.shared.b16 {%0,%1,%2,%3}, [%4];"
                 : "=r"(r0), "=r"(r1), "=r"(r2), "=r"(r3) : "r"(a));
}

__device__ __forceinline__ void hmma(float* c, const unsigned* a, const unsigned* b) {
    asm volatile(
        "mma.sync.aligned.m16n8k16.row.col.f32.f16.f16.f32 "
        "{%0,%1,%2,%3}, {%4,%5,%6,%7}, {%8,%9}, {%0,%1,%2,%3};"
        : "+f"(c[0]), "+f"(c[1]), "+f"(c[2]), "+f"(c[3])
        : "r"(a[0]), "r"(a[1]), "r"(a[2]), "r"(a[3]), "r"(b[0]), "r"(b[1]));
}

// ---------------- zero counters ----------------
__global__ void k_zero() {
    if (threadIdx.x < E_NUM) g_cnt[threadIdx.x] = 0;
}

// ========= front kernel: gate blocks (0..2047) + conv of w1,kw only =========
#define CONVF_BLOCKS 2560
__global__ void k_front(const float* __restrict__ x,
                        const float* __restrict__ gate_w,
                        const float* __restrict__ sgw,
                        const float4* __restrict__ w1,
                        const float4* __restrict__ kw) {
    const int tid = threadIdx.x;
    if (blockIdx.x >= N_TOK) {
        const int N1 = E_NUM * H_DIM * C_DIM / 4;
        const int N2 = N1 + H_DIM * C_DIM / 4;
        const int cb = blockIdx.x - N_TOK;
        const int stride = CONVF_BLOCKS * 256;
        for (int i = cb * 256 + tid; i < N2; i += stride) {
            const float4* s;
            __half2* d;
            int j;
            if (i < N1) { s = w1; d = (__half2*)g_w1; j = i; }
            else        { s = kw; d = (__half2*)g_kw; j = i - N1; }
            float4 v = s[j];
            d[2 * j] = __halves2half2(__float2half_rn(v.x), __float2half_rn(v.y));
            d[2 * j + 1] = __halves2half2(__float2half_rn(v.z), __float2half_rn(v.w));
        }
        return;
    }
    // ---- gate path: rmsnorm + routing for token n ----
    const int n = blockIdx.x, wid = tid >> 5, lid = tid & 31;
    __shared__ float part[10][8];
    __shared__ float sc[2];
    __shared__ float logits[9];

    float4 v = reinterpret_cast<const float4*>(x + (size_t)n * C_DIM)[tid];
    float ss = v.x * v.x + v.y * v.y + v.z * v.z + v.w * v.w;
#pragma unroll
    for (int o = 16; o; o >>= 1) ss += __shfl_xor_sync(0xffffffffu, ss, o);
    if (lid == 0) part[9][wid] = ss;
    __syncthreads();
    if (tid == 0) {
        float s = 0;
#pragma unroll
        for (int w = 0; w < 8; w++) s += part[9][w];
        float m1 = s * (1.0f / C_DIM);
        float r1 = rsqrtf(m1 + EPSF);
        sc[0] = r1;
        sc[1] = rsqrtf(m1 * r1 * r1 + EPSF);
    }
    __syncthreads();
    const float r1 = sc[0], r2 = sc[1];

    float4 xt = {v.x * r1, v.y * r1, v.z * r1, v.w * r1};
    float4 xs = {xt.x * r2, xt.y * r2, xt.z * r2, xt.w * r2};
    size_t base = (size_t)n * C_DIM + tid * 4;
    {
        __half2* p = (__half2*)(g_xt + base);
        p[0] = __halves2half2(__float2half_rn(xt.x), __float2half_rn(xt.y));
        p[1] = __halves2half2(__float2half_rn(xt.z), __float2half_rn(xt.w));
        __half2* q = (__half2*)(g_xs + base);
        q[0] = __halves2half2(__float2half_rn(xs.x), __float2half_rn(xs.y));
        q[1] = __halves2half2(__float2half_rn(xs.z), __float2half_rn(xs.w));
    }

    float acc[9];
#pragma unroll
    for (int e = 0; e < 8; e++) {
        float4 g = reinterpret_cast<const float4*>(gate_w + (size_t)e * C_DIM)[tid];
        acc[e] = xt.x * g.x + xt.y * g.y + xt.z * g.z + xt.w * g.w;
    }
    {
        float4 g = reinterpret_cast<const float4*>(sgw)[tid];
        acc[8] = xt.x * g.x + xt.y * g.y + xt.z * g.z + xt.w * g.w;
    }
#pragma unroll
    for (int e = 0; e < 9; e++) {
        float a = acc[e];
#pragma unroll
        for (int o = 16; o; o >>= 1) a += __shfl_xor_sync(0xffffffffu, a, o);
        if (lid == 0) part[e][wid] = a;
    }
    __syncthreads();
    if (wid == 0 && lid < 9) {
        float s = 0;
#pragma unroll
        for (int w = 0; w < 8; w++) s += part[lid][w];
        logits[lid] = s;
    }
    __syncthreads();

    if (tid == 0) {
        float mx = logits[0];
#pragma unroll
        for (int e = 1; e < 8; e++) mx = fmaxf(mx, logits[e]);
        float sum = 0.0f, sv[8];
#pragma unroll
        for (int e = 0; e < 8; e++) { sv[e] = expf(logits[e] - mx); sum += sv[e]; }
        float inv = 1.0f / sum;
#pragma unroll
        for (int e = 0; e < 8; e++) { sv[e] *= inv; g_scores[n * 8 + e] = sv[e]; }
        int i1 = 0;
#pragma unroll
        for (int e = 1; e < 8; e++) if (sv[e] > sv[i1]) i1 = e;
        int i2 = (i1 == 0) ? 1 : 0;
#pragma unroll
        for (int e = 0; e < 8; e++) if (e != i1 && sv[e] > sv[i2]) i2 = e;
        float wa = sv[i1], wb = sv[i2];
        float wi = 1.0f / (wa + wb + 1e-6f);
        int p1 = atomicAdd(&g_cnt[i1], 1);
        g_etok[i1 * N_TOK + p1] = n;
        g_ew[i1 * N_TOK + p1] = wa * wi;
        g_eslot[i1 * N_TOK + p1] = 2 * n;
        int p2 = atomicAdd(&g_cnt[i2], 1);
        g_etok[i2 * N_TOK + p2] = n;
        g_ew[i2 * N_TOK + p2] = wb * wi;
        g_eslot[i2 * N_TOK + p2] = 2 * n + 1;
        g_sg[n] = 1.0f / (1.0f + expf(-logits[8]));
    }
}

// ===== HMMA fp16 single-pass GEMM, 3-stage ring / 1 barrier per chunk, BK=64 =====
// CTA tile 128 x TN, BK=64, 256 thr.
// MODE 0 grid z=10: z<8 expert up; z==8 shared up; z==9 service slice
//   (grid-stride conv of w2+vw; flat block 255 also computes aux loss).
#define BKC 64
#define ROWB 144                 // 128B data + 16B pad; conflict-free ldmatrix
#define STAGES 3

template <int MODE, int TN>
__global__ void __launch_bounds__(256, 2) k_mma(const float* __restrict__ bias,
                                                float* __restrict__ outp,
                                                const float4* __restrict__ cw2,
                                                const float4* __restrict__ cvw,
                                                float* __restrict__ auxout,
                                                int out_size) {
    constexpr int W_M = 4;
    constexpr int W_N = 2;
    constexpr int WTM = 128 / W_M;               // 32
    constexpr int WTN = TN / W_N;                // 64 or 32
    constexpr int MF = WTM / 16;                 // 2
    constexpr int NF = WTN / 8;                  // 8 or 4
    constexpr int A_SZ = 128 * ROWB;
    constexpr int B_SZ = TN * ROWB;
    constexpr int SA = 0;
    constexpr int SB = A_SZ;
    constexpr int BUF_SZ = A_SZ + B_SZ;

    const int tid = threadIdx.x;

    // ---------- service slice: conv(w2, vw) + aux (MODE 0, z==9) ----------
    if (MODE == 0 && blockIdx.z == 9) {
        const int fid = blockIdx.y * gridDim.x + blockIdx.x;   // 0..255
        if (fid < 255) {
            const int NW2 = E_NUM * C_DIM * H_DIM / 4;
            const int NS = NW2 + C_DIM * H_DIM / 4;
            const int stride = 255 * 256;
            for (int i = fid * 256 + tid; i < NS; i += stride) {
                const float4* s;
                __half2* d;
                int j;
                if (i < NW2) { s = cw2; d = (__half2*)g_w2; j = i; }
                else         { s = cvw; d = (__half2*)g_vw; j = i - NW2; }
                float4 v = s[j];
                d[2 * j] = __halves2half2(__float2half_rn(v.x), __float2half_rn(v.y));
                d[2 * j + 1] = __halves2half2(__float2half_rn(v.z), __float2half_rn(v.w));
            }
        } else {
            // aux loss reduction
            __shared__ float red[256];
            __shared__ float ssum[8];
            float loc[8] = {0, 0, 0, 0, 0, 0, 0, 0};
            for (int n = tid; n < N_TOK; n += 256) {
#pragma unroll
                for (int e2 = 0; e2 < 8; e2++) loc[e2] += g_scores[n * 8 + e2];
            }
#pragma unroll 1
            for (int e2 = 0; e2 < 8; e2++) {
                red[tid] = loc[e2];
                __syncthreads();
                for (int s = 128; s > 0; s >>= 1) {
                    if (tid < s) red[tid] += red[tid + s];
                    __syncthreads();
                }
                if (tid == 0) ssum[e2] = red[0];
                __syncthreads();
            }
            if (tid == 0) {
                float aux = 0.0f;
#pragma unroll
                for (int e2 = 0; e2 < 8; e2++)
                    aux += ((float)g_cnt[e2] * 0.5f / N_TOK) * (ssum[e2] / N_TOK);
                aux *= (float)E_NUM * 0.01f;
                if (out_size > N_TOK * C_DIM) auxout[N_TOK * C_DIM] = aux;
            }
        }
        return;
    }

    extern __shared__ char dsm[];
    __shared__ int s_row[128];
    __shared__ int s_slot[128];
    __shared__ float s_w[128];

    const int e = blockIdx.z;
    const bool shared_path = (MODE == 0 && e == 8);
    const int cnt = (MODE == 0 && !shared_path) ? g_cnt[e]
                  : (MODE == 1) ? g_cnt[e] : N_TOK;
    const int m0 = blockIdx.y * 128;
    if (m0 >= cnt) return;
    const int n0 = blockIdx.x * TN;
    const int K = (MODE == 0) ? C_DIM : H_DIM;

    const __half *A, *B;
    if (MODE == 0) {
        if (shared_path) { A = g_xs; B = g_kw; }
        else { A = g_xt; B = g_w1 + (size_t)e * H_DIM * C_DIM; }
    } else if (MODE == 1) {
        A = g_h; B = g_w2 + (size_t)e * C_DIM * H_DIM;
    } else {
        A = g_kk; B = g_vw;
    }

    const int wid = tid >> 5, lid = tid & 31;
    const int wm = wid / W_N, wn = wid % W_N;

    if (tid < 128) {
        int mi = m0 + tid;
        if (mi >= cnt) mi = cnt - 1;
        if (MODE == 0 && !shared_path) {
            s_row[tid] = g_etok[e * N_TOK + mi];
            s_slot[tid] = g_eslot[e * N_TOK + mi];
            s_w[tid] = g_ew[e * N_TOK + mi];
        } else if (MODE == 1) {
            int sl = g_eslot[e * N_TOK + mi];
            s_row[tid] = sl;
            s_slot[tid] = sl;
        } else {
            s_row[tid] = mi;
        }
    }
    __syncthreads();

    const unsigned sbase = smem_u32(dsm);
    const int lr = tid >> 3;          // 0..31: row group (32 rows per pass)
    const int lcb = (tid & 7) << 4;   // byte col 0..112
    const int lce = (tid & 7) << 3;   // elem col 0..56

    auto load_chunk = [&](int c, int b) {
        const int kc = c * BKC;
        const unsigned bufb = sbase + b * BUF_SZ;
#pragma unroll
        for (int i = 0; i < 4; i++) {           // A: 128 rows
            const int r = lr + i * 32;
            const unsigned so = r * ROWB + lcb;
            const size_t ga = (size_t)s_row[r] * K + kc + lce;
            CP16(bufb + SA + so, A + ga);
        }
#pragma unroll
        for (int i = 0; i < TN / 32; i++) {     // B: TN rows
            const int r = lr + i * 32;
            const unsigned so = r * ROWB + lcb;
            const size_t gb = (size_t)(n0 + r) * K + kc + lce;
            CP16(bufb + SB + so, B + gb);
        }
        CP_COMMIT();
    };

    float acc[MF][NF][4];
#pragma unroll
    for (int i = 0; i < MF; i++)
#pragma unroll
        for (int j = 0; j < NF; j++)
#pragma unroll
            for (int q = 0; q < 4; q++) acc[i][j][q] = 0.0f;

    const unsigned aoff = (unsigned)((wm * WTM + (lid & 7) + ((lid >> 3) & 1) * 8) * ROWB +
                                     ((lid >> 4) & 1) * 16);
    const unsigned boff = (unsigned)((wn * WTN + (lid & 7) + ((lid >> 4) & 1) * 8) * ROWB +
                                     ((lid >> 3) & 1) * 16);
    const int NC = K / BKC;
    load_chunk(0, 0);

    int buf = 0;
    for (int c = 0; c < NC; c++) {
        if (c + 1 < NC) { load_chunk(c + 1, (c + 1) % STAGES); CP_WAIT1(); }
        else CP_WAIT0();
        __syncthreads();                         // single barrier per chunk
        const unsigned bufb = sbase + buf * BUF_SZ;
#pragma unroll
        for (int k16 = 0; k16 < 4; k16++) {      // BK=64 -> 4 k16 steps
            const unsigned kb = k16 * 32;
            unsigned af[MF][4], bf[NF][2];
#pragma unroll
            for (int pr = 0; pr < NF / 2; pr++) {
                const unsigned a = bufb + boff + pr * (16 * ROWB) + kb;
                ldsm4(bf[2 * pr][0], bf[2 * pr][1], bf[2 * pr + 1][0], bf[2 * pr + 1][1], a + SB);
            }
#pragma unroll
            for (int mt = 0; mt < MF; mt++) {
                const unsigned a = bufb + aoff + mt * (16 * ROWB) + kb;
                ldsm4(af[mt][0], af[mt][1], af[mt][2], af[mt][3], a + SA);
            }
#pragma unroll
            for (int mt = 0; mt < MF; mt++)
#pragma unroll
                for (int nt = 0; nt < NF; nt++) hmma(acc[mt][nt], af[mt], bf[nt]);
        }
        buf = (buf + 1) % STAGES;
    }

    // ---------------- epilogue ----------------
    const int rbase = wm * WTM + (lid >> 2);
    const int cbase = n0 + wn * WTN + 2 * (lid & 3);
#pragma unroll
    for (int mt = 0; mt < MF; mt++) {
#pragma unroll
        for (int half = 0; half < 2; half++) {
            const int rl = rbase + mt * 16 + half * 8;   // local row 0..127
            if (m0 + rl >= cnt) continue;
#pragma unroll
            for (int nt = 0; nt < NF; nt++) {
                const int cg = cbase + nt * 8;
                float v0 = acc[mt][nt][2 * half];
                float v1 = acc[mt][nt][2 * half + 1];
                if (MODE == 0) {
                    if (!shared_path) {
                        const float w = s_w[rl];
                        const int slot = s_slot[rl];
                        v0 = fmaxf(v0, 0.0f); v0 = v0 * v0 * w;
                        v1 = fmaxf(v1, 0.0f); v1 = v1 * v1 * w;
                        *(__half2*)(g_h + (size_t)slot * H_DIM + cg) =
                            __halves2half2(__float2half_rn(v0), __float2half_rn(v1));
                    } else {
                        const int m = m0 + rl;
                        v0 += bias[cg]; v1 += bias[cg + 1];
                        v0 = fmaxf(v0, 0.0f); v0 = v0 * v0;
                        v1 = fmaxf(v1, 0.0f); v1 = v1 * v1;
                        *(__half2*)(g_kk + (size_t)m * H_DIM + cg) =
                            __halves2half2(__float2half_rn(v0), __float2half_rn(v1));
                    }
                } else if (MODE == 1) {
                    const int slot = s_slot[rl];
                    *(float2*)(g_contrib + (size_t)slot * C_DIM + cg) = make_float2(v0, v1);
                } else {
                    const int m = m0 + rl;
                    const float sg = g_sg[m];
                    float2 c0 = *(const float2*)(g_contrib + (size_t)(2 * m) * C_DIM + cg);
                    float2 c1 = *(const float2*)(g_contrib + (size_t)(2 * m + 1) * C_DIM + cg);
                    *(float2*)(outp + (size_t)m * C_DIM + cg) =
                        make_float2(sg * (v0 + bias[cg]) + c0.x + c1.x,
                                    sg * (v1 + bias[cg + 1]) + c0.y + c1.y);
                }
            }
        }
    }
}

// ---------------- launch ----------------
#define DS128 (STAGES * (128 * ROWB + 128 * ROWB))   // 110592, OCC=2
#define DS64  (STAGES * (128 * ROWB + 64 * ROWB))    // 82944, OCC=2

extern "C" void kernel_launch(void* const* d_in, const int* in_sizes, int n_in,
                              void* d_out, int out_size) {
    const float* x   = (const float*)d_in[0];
    const float* gw  = (const float*)d_in[1];
    const float* w1  = (const float*)d_in[2];
    const float* w2  = (const float*)d_in[3];
    const float* sgw = (const float*)d_in[4];
    const float* kw  = (const float*)d_in[5];
    const float* kb  = (const float*)d_in[6];
    const float* vw  = (const float*)d_in[7];
    const float* vb  = (const float*)d_in[8];
    float* out = (float*)d_out;

    static int attr_done = 0;
    if (!attr_done) {
        cudaFuncSetAttribute((const void*)k_mma<0, 128>,
                             cudaFuncAttributeMaxDynamicSharedMemorySize, DS128);
        cudaFuncSetAttribute((const void*)k_mma<1, 128>,
                             cudaFuncAttributeMaxDynamicSharedMemorySize, DS128);
        cudaFuncSetAttribute((const void*)k_mma<3, 64>,
                             cudaFuncAttributeMaxDynamicSharedMemorySize, DS64);
        attr_done = 1;
    }

    k_zero<<<1, 32>>>();
    k_front<<<N_TOK + CONVF_BLOCKS, 256>>>(x, gw, sgw,
                                           (const float4*)w1, (const float4*)kw);

    // expert up + shared up + service slice (conv w2/vw + aux)
    k_mma<0, 128><<<dim3(16, 16, 10), 256, DS128>>>(kb, nullptr,
                                                    (const float4*)w2, (const float4*)vw,
                                                    out, out_size);
    // expert down
    k_mma<1, 128><<<dim3(8, 16, 8), 256, DS128>>>(nullptr, nullptr,
                                                  nullptr, nullptr, nullptr, 0);
    // shared down + combine
    k_mma<3, 64><<<dim3(16, 16, 1), 256, DS64>>>(vb, out,
                                                 nullptr, nullptr, nullptr, 0);
}